// round 13
// baseline (speedup 1.0000x reference)
#include <cuda_runtime.h>
#include <math_constants.h>

#define IMG_H 64
#define IMG_W 2048
#define KNN_CUTOFF 1.0f

#define PTS_PER_WARP 12           // 2 points per 5-lane group, 6 groups
#define WARPS_PER_BLK 8
#define THREADS_FUSED (WARPS_PER_BLK * 32)          // 256
#define PTS_PER_BLK (WARPS_PER_BLK * PTS_PER_WARP)  // 96

// inv_g[k] = 1 - gauss(k)/sum(gauss), sigma=1, 5x5, row-major (ky,kx)
__device__ __constant__ float INV_G_C[25] = {
    0.99703098f, 0.98669378f, 0.97806177f, 0.98669378f, 0.99703098f,
    0.98669378f, 0.94036569f, 0.90167956f, 0.94036569f, 0.98669378f,
    0.97806177f, 0.90167956f, 0.83789717f, 0.90167956f, 0.97806177f,
    0.98669378f, 0.94036569f, 0.90167956f, 0.94036569f, 0.98669378f,
    0.99703098f, 0.98669378f, 0.97806177f, 0.98669378f, 0.99703098f
};

// ---------------------------------------------------------------------------
// COLD path (~65 of 131072 points): exact top-5 with reference tie-breaking.
// __noinline__ so its registers don't pollute the hot path.
// ---------------------------------------------------------------------------
__device__ __noinline__
unsigned knn_exact_top5(const float* __restrict__ proj_range,
                        int x0, int y0, float ur)
{
    unsigned key[25];
    unsigned ib = 0;
#pragma unroll
    for (int k = 0; k < 25; ++k) {
        const int yy = y0 + (k / 5) - 2;
        const int xx = x0 + (k % 5) - 2;
        const bool valid = ((unsigned)yy < (unsigned)IMG_H) &&
                           ((unsigned)xx < (unsigned)IMG_W);
        const int yyc = valid ? yy : 0;
        const int xxc = valid ? xx : 0;
        float rr = valid ? __ldg(proj_range + yyc * IMG_W + xxc) : 0.0f;
        if (rr < 0.0f) rr = CUDART_INF_F;   // matches reference
        if (k == 12)   rr = ur;             // center: d = 0
        key[k] = __float_as_uint(fabsf(rr - ur) * INV_G_C[k]);
        if (valid) ib |= (1u << k);
    }

    unsigned nm = 0;
#pragma unroll
    for (int sel = 0; sel < 5; ++sel) {
        unsigned long long best = ~0ull;
#pragma unroll
        for (int k = 0; k < 25; ++k) {
            const unsigned long long c =
                ((unsigned long long)key[k] << 32) | (unsigned)k;
            if (c < best) best = c;
        }
        const unsigned bi = (unsigned)(best & 0xFFFFFFFFu);
        nm |= (1u << bi);     // all 5 winners have d <= cutoff (>5 passers exist)
#pragma unroll
        for (int k = 0; k < 25; ++k)
            if ((unsigned)k == bi) key[k] = 0xFFFFFFFFu;
    }

    return nm & ib;           // OOB winners contribute zero probs: drop
}

// Build this lane's row masks from two preloaded quads (interior points).
// Weights wb0/wb1/wb2 are per-lane registers (center/mid/outer column).
__device__ __forceinline__
void row_mask_quads(float4 lo, float4 hi, bool rv, int off, int r, float ur,
                    float wb0, float wb1, float wb2,
                    unsigned& partAll, unsigned& partIB)
{
    const bool b1 = (off & 2) != 0;
    const bool b0 = (off & 1) != 0;
    const float h0 = b1 ? lo.z : lo.x;
    const float h1 = b1 ? lo.w : lo.y;
    const float h2 = b1 ? hi.x : lo.z;
    const float h3 = b1 ? hi.y : lo.w;
    const float h4 = b1 ? hi.z : hi.x;
    const float h5 = b1 ? hi.w : hi.y;
    float wv[5];
    wv[0] = b0 ? h1 : h0;
    wv[1] = b0 ? h2 : h1;
    wv[2] = b0 ? h3 : h2;
    wv[3] = b0 ? h4 : h3;
    wv[4] = b0 ? h5 : h4;
    const float w[5] = { wb2, wb1, wb0, wb1, wb2 };
#pragma unroll
    for (int i = 0; i < 5; ++i) {
        const int k = r * 5 + i;
        const float rr = rv ? wv[i] : 0.0f;        // OOB row = unfold zero-pad
        const float d  = fabsf(rr - ur) * w[i];    // exact reference arithmetic
        const bool pass = (d <= KNN_CUTOFF) && (rr >= 0.0f);
        if (pass)       partAll |= (1u << k);
        if (pass && rv) partIB  |= (1u << k);
    }
}

// Edge-column (~0.25%) row masks via scalar clamped loads.
__device__ __forceinline__
void row_mask_edge(const float* __restrict__ proj_range,
                   int x0, int yyc, bool rv, int r, float ur,
                   float wb0, float wb1, float wb2,
                   unsigned& partAll, unsigned& partIB)
{
    const float w[5] = { wb2, wb1, wb0, wb1, wb2 };
#pragma unroll
    for (int i = 0; i < 5; ++i) {
        const int k  = r * 5 + i;
        const int xx = x0 + i - 2;
        const bool valid = rv && ((unsigned)xx < (unsigned)IMG_W);
        const int xxc = valid ? xx : 0;
        const float rawr = __ldg(proj_range + yyc * IMG_W + xxc);
        const float rr = valid ? rawr : 0.0f;
        const float d  = fabsf(rr - ur) * w[i];
        const bool pass = (d <= KNN_CUTOFF) && (rr >= 0.0f);
        if (pass)          partAll |= (1u << k);
        if (pass && valid) partIB  |= (1u << k);
    }
}

// Gather this lane's channel chunk r for the <=5 winners in maskIB and store.
__device__ __forceinline__
void gather_store(const float4* __restrict__ probs4,
                  float4* __restrict__ out4,
                  unsigned maskIB, int base, int p, int r)
{
    int kk[5];
    unsigned mm = maskIB;
#pragma unroll
    for (int i = 0; i < 5; ++i) {
        kk[i] = __ffs(mm) - 1;                 // -1 when exhausted
        mm &= mm - 1;
    }
    float4 acc = make_float4(0.f, 0.f, 0.f, 0.f);
#pragma unroll
    for (int i = 0; i < 5; ++i) {
        const int k  = kk[i];
        const int ky = (k * 205) >> 10;        // k/5 for k in [0,24]
        const int idx = base + k + ky * 2043 - 4098;  // = base+(ky-2)*W+(kx-2)
        if (k >= 0) {
            const float4 v = __ldg(probs4 + (size_t)idx * 5 + r);
            acc.x += v.x; acc.y += v.y; acc.z += v.z; acc.w += v.w;
        }
    }
    out4[(size_t)p * 5 + r] = acc;             // coalesced 80B per point
}

// ---------------------------------------------------------------------------
// Fused kernel: 5 lanes/point, TWO points per lane-group (12 per warp),
// software-pipelined: all range loads issue before mask/gather compute.
// No smem, no __syncthreads; masks combined via warp shuffles.
// ---------------------------------------------------------------------------
__global__ __launch_bounds__(THREADS_FUSED, 5)
void knn_fused(const float*  __restrict__ proj_range,
               const float*  __restrict__ unproj,
               const float4* __restrict__ probs4,    // [H*W][5] float4
               const int*    __restrict__ px,
               const int*    __restrict__ py,
               float4*       __restrict__ out4,      // [P][5] float4
               int P)
{
    const int tid   = threadIdx.x;
    const int wrp   = tid >> 5;
    const int lane  = tid & 31;
    const int g     = (lane * 205) >> 10;      // lane / 5 (0..6)
    const int r     = lane - g * 5;            // role: row / channel chunk
    const int wbase = blockIdx.x * PTS_PER_BLK + wrp * PTS_PER_WARP;
    const int pA    = wbase + g;
    const int pB    = pA + 6;
    const bool laneOK = (lane < 30);
    const bool actA = laneOK && (pA < P);
    const bool actB = laneOK && (pB < P);

    // per-lane row weights (r fixed per lane -> no dynamic constant indexing)
    const int a = (r >= 2) ? (r - 2) : (2 - r);          // |r-2|
    const float wb0 = (a == 0) ? 0.83789717f : ((a == 1) ? 0.90167956f : 0.97806177f);
    const float wb1 = (a == 0) ? 0.90167956f : ((a == 1) ? 0.94036569f : 0.98669378f);
    const float wb2 = (a == 0) ? 0.97806177f : ((a == 1) ? 0.98669378f : 0.99703098f);

    // ---------------- front-load ALL metadata + range quads --------------
    int xA = 0, yA = 0, xB = 0, yB = 0;
    float urA = 0.0f, urB = 0.0f;
    if (actA) { xA = px[pA]; yA = py[pA]; urA = unproj[pA]; }
    if (actB) { xB = px[pB]; yB = py[pB]; urB = unproj[pB]; }

    const int  yyA  = yA + r - 2;
    const bool rvA  = ((unsigned)yyA < (unsigned)IMG_H);
    const int  yycA = rvA ? yyA : 0;
    const bool intA = actA && (xA >= 2) && (xA <= IMG_W - 3);
    const int  offA = (xA - 2) & 3;
    const int  bsA  = (xA - 2) & ~3;

    const int  yyB  = yB + r - 2;
    const bool rvB  = ((unsigned)yyB < (unsigned)IMG_H);
    const int  yycB = rvB ? yyB : 0;
    const bool intB = actB && (xB >= 2) && (xB <= IMG_W - 3);
    const int  offB = (xB - 2) & 3;
    const int  bsB  = (xB - 2) & ~3;

    float4 loA, hiA, loB, hiB;
    if (intA) {
        const float4* rp = (const float4*)(proj_range + yycA * IMG_W + bsA);
        loA = __ldg(rp); hiA = __ldg(rp + 1);
    }
    if (intB) {
        const float4* rp = (const float4*)(proj_range + yycB * IMG_W + bsB);
        loB = __ldg(rp); hiB = __ldg(rp + 1);
    }

    // ---------------- phase 1: row masks for A then B ---------------------
    unsigned partAllA = 0, partIBA = 0, partAllB = 0, partIBB = 0;
    if (intA)      row_mask_quads(loA, hiA, rvA, offA, r, urA, wb0, wb1, wb2, partAllA, partIBA);
    else if (actA) row_mask_edge(proj_range, xA, yycA, rvA, r, urA, wb0, wb1, wb2, partAllA, partIBA);
    if (intB)      row_mask_quads(loB, hiB, rvB, offB, r, urB, wb0, wb1, wb2, partAllB, partIBB);
    else if (actB) row_mask_edge(proj_range, xB, yycB, rvB, r, urB, wb0, wb1, wb2, partAllB, partIBB);

    // ---------------- combine within 5-lane groups via shuffles ----------
    const int gb = lane - r;                   // group base lane
    unsigned maskAllA = partAllA, maskIBA = partIBA;
    unsigned maskAllB = partAllB, maskIBB = partIBB;
#pragma unroll
    for (int j = 1; j < 5; ++j) {
        const int src = gb + ((r + j >= 5) ? (r + j - 5) : (r + j));
        maskAllA |= __shfl_sync(0xFFFFFFFFu, partAllA, src);
        maskIBA  |= __shfl_sync(0xFFFFFFFFu, partIBA,  src);
        maskAllB |= __shfl_sync(0xFFFFFFFFu, partAllB, src);
        maskIBB  |= __shfl_sync(0xFFFFFFFFu, partIBB,  src);
    }

    maskAllA |= (1u << 12); maskIBA |= (1u << 12);  // center always contributes
    maskAllB |= (1u << 12); maskIBB |= (1u << 12);

    // rare overflow (>5 cutoff passers, ~5e-4): cold exact recompute
    if (actA && __popc(maskAllA) > 5) maskIBA = knn_exact_top5(proj_range, xA, yA, urA);
    if (actB && __popc(maskAllB) > 5) maskIBB = knn_exact_top5(proj_range, xB, yB, urB);

    // ---------------- phase 2: gathers (A and B independent -> MLP) ------
    if (actA) gather_store(probs4, out4, maskIBA, yA * IMG_W + xA, pA, r);
    if (actB) gather_store(probs4, out4, maskIBB, yB * IMG_W + xB, pB, r);
}

extern "C" void kernel_launch(void* const* d_in, const int* in_sizes, int n_in,
                              void* d_out, int out_size)
{
    const float*  proj_range = (const float*)  d_in[0];
    const float*  unproj     = (const float*)  d_in[1];
    const float4* probs4     = (const float4*) d_in[2];
    const int*    px         = (const int*)    d_in[3];
    const int*    py         = (const int*)    d_in[4];
    float4*       out4       = (float4*)       d_out;

    const int P = in_sizes[1];           // unproj_range element count
    const int blocks = (P + PTS_PER_BLK - 1) / PTS_PER_BLK;
    knn_fused<<<blocks, THREADS_FUSED>>>(proj_range, unproj, probs4,
                                         px, py, out4, P);
}

// round 14
// speedup vs baseline: 1.0019x; 1.0019x over previous
#include <cuda_runtime.h>
#include <math_constants.h>

#define IMG_H 64
#define IMG_W 2048
#define KNN_CUTOFF 1.0f

#define PTS_PER_WARP 6            // 30 active lanes, 2 idle
#define WARPS_PER_BLK 8
#define THREADS_FUSED (WARPS_PER_BLK * 32)          // 256
#define PTS_PER_BLK (WARPS_PER_BLK * PTS_PER_WARP)  // 48

// inv_g[k] = 1 - gauss(k)/sum(gauss), sigma=1, 5x5, row-major (ky,kx)
__device__ __constant__ float INV_G_C[25] = {
    0.99703098f, 0.98669378f, 0.97806177f, 0.98669378f, 0.99703098f,
    0.98669378f, 0.94036569f, 0.90167956f, 0.94036569f, 0.98669378f,
    0.97806177f, 0.90167956f, 0.83789717f, 0.90167956f, 0.97806177f,
    0.98669378f, 0.94036569f, 0.90167956f, 0.94036569f, 0.98669378f,
    0.99703098f, 0.98669378f, 0.97806177f, 0.98669378f, 0.99703098f
};

// ---------------------------------------------------------------------------
// COLD path (~65 of 131072 points): exact top-5 with reference tie-breaking.
// __noinline__ so its registers don't pollute the hot path.
// ---------------------------------------------------------------------------
__device__ __noinline__
unsigned knn_exact_top5(const float* __restrict__ proj_range,
                        int x0, int y0, float ur)
{
    unsigned key[25];
    unsigned ib = 0;
#pragma unroll
    for (int k = 0; k < 25; ++k) {
        const int yy = y0 + (k / 5) - 2;
        const int xx = x0 + (k % 5) - 2;
        const bool valid = ((unsigned)yy < (unsigned)IMG_H) &&
                           ((unsigned)xx < (unsigned)IMG_W);
        const int yyc = valid ? yy : 0;
        const int xxc = valid ? xx : 0;
        float rr = valid ? __ldg(proj_range + yyc * IMG_W + xxc) : 0.0f;
        if (rr < 0.0f) rr = CUDART_INF_F;   // matches reference
        if (k == 12)   rr = ur;             // center: d = 0
        key[k] = __float_as_uint(fabsf(rr - ur) * INV_G_C[k]);
        if (valid) ib |= (1u << k);
    }

    unsigned nm = 0;
#pragma unroll
    for (int sel = 0; sel < 5; ++sel) {
        unsigned long long best = ~0ull;
#pragma unroll
        for (int k = 0; k < 25; ++k) {
            const unsigned long long c =
                ((unsigned long long)key[k] << 32) | (unsigned)k;
            if (c < best) best = c;
        }
        const unsigned bi = (unsigned)(best & 0xFFFFFFFFu);
        nm |= (1u << bi);     // all 5 winners have d <= cutoff (>5 passers exist)
#pragma unroll
        for (int k = 0; k < 25; ++k)
            if ((unsigned)k == bi) key[k] = 0xFFFFFFFFu;
    }

    return nm & ib;           // OOB winners contribute zero probs: drop
}

// ---------------------------------------------------------------------------
// Fused kernel: 5 lanes/point, 6 points/warp (lanes 30,31 idle).
// Phase 1 (role = window row): build cutoff mask; combine via warp shuffles.
// Phase 2 (role = channel chunk): gather probs for mask winners, store.
// No smem, no __syncthreads. Forced to <=32 regs for 100% occupancy.
// ---------------------------------------------------------------------------
__global__ __launch_bounds__(THREADS_FUSED, 8)
void knn_fused(const float*  __restrict__ proj_range,
               const float*  __restrict__ unproj,
               const float4* __restrict__ probs4,    // [H*W][5] float4
               const int*    __restrict__ px,
               const int*    __restrict__ py,
               float4*       __restrict__ out4,      // [P][5] float4
               int P)
{
    const int tid   = threadIdx.x;
    const int wrp   = tid >> 5;
    const int lane  = tid & 31;
    const int g     = (lane * 205) >> 10;      // lane / 5 (0..6)
    const int r     = lane - g * 5;            // role: row / channel chunk
    const int p     = blockIdx.x * PTS_PER_BLK + wrp * PTS_PER_WARP + g;
    const bool active = (lane < 30) && (p < P);

    // per-lane row weights (r fixed per lane -> no dynamic constant indexing)
    const int a = (r >= 2) ? (r - 2) : (2 - r);          // |r-2|
    const float wb0 = (a == 0) ? 0.83789717f : ((a == 1) ? 0.90167956f : 0.97806177f);
    const float wb1 = (a == 0) ? 0.90167956f : ((a == 1) ? 0.94036569f : 0.98669378f);
    const float wb2 = (a == 0) ? 0.97806177f : ((a == 1) ? 0.98669378f : 0.99703098f);

    int x0 = 0, y0 = 0;
    float ur = 0.0f;

    // ---------------- phase 1: this lane's window row --------------------
    unsigned partAll = 0, partIB = 0;
    if (active) {
        x0 = px[p];
        y0 = py[p];
        ur = unproj[p];

        const int yy  = y0 + r - 2;
        const bool rv = ((unsigned)yy < (unsigned)IMG_H);
        const int yyc = rv ? yy : 0;
        const float w[5] = { wb2, wb1, wb0, wb1, wb2 };

        if (x0 >= 2 && x0 <= IMG_W - 3) {
            const int xb   = x0 - 2;
            const int base = xb & ~3;          // aligned; W%4==0 so in-range
            const bool b1  = (xb & 2) != 0;
            const bool b0  = (xb & 1) != 0;
            const float4* rp = (const float4*)(proj_range + yyc * IMG_W + base);
            const float4 lo = __ldg(rp);
            const float4 hi = __ldg(rp + 1);
            const float h0 = b1 ? lo.z : lo.x;
            const float h1 = b1 ? lo.w : lo.y;
            const float h2 = b1 ? hi.x : lo.z;
            const float h3 = b1 ? hi.y : lo.w;
            const float h4 = b1 ? hi.z : hi.x;
            const float h5 = b1 ? hi.w : hi.y;
            float wv[5];
            wv[0] = b0 ? h1 : h0;
            wv[1] = b0 ? h2 : h1;
            wv[2] = b0 ? h3 : h2;
            wv[3] = b0 ? h4 : h3;
            wv[4] = b0 ? h5 : h4;
#pragma unroll
            for (int i = 0; i < 5; ++i) {
                const int k = r * 5 + i;
                const float rr = rv ? wv[i] : 0.0f;   // OOB row = unfold zero-pad
                const float d  = fabsf(rr - ur) * w[i];
                const bool pass = (d <= KNN_CUTOFF) && (rr >= 0.0f);
                if (pass)       partAll |= (1u << k);
                if (pass && rv) partIB  |= (1u << k);
            }
        } else {
            // edge columns (~0.25%): scalar clamped loads for this row
#pragma unroll
            for (int i = 0; i < 5; ++i) {
                const int k  = r * 5 + i;
                const int xx = x0 + i - 2;
                const bool valid = rv && ((unsigned)xx < (unsigned)IMG_W);
                const int xxc = valid ? xx : 0;
                const float rawr = __ldg(proj_range + yyc * IMG_W + xxc);
                const float rr = valid ? rawr : 0.0f;
                const float d  = fabsf(rr - ur) * w[i];
                const bool pass = (d <= KNN_CUTOFF) && (rr >= 0.0f);
                if (pass)          partAll |= (1u << k);
                if (pass && valid) partIB  |= (1u << k);
            }
        }
    }

    // ---------------- combine within 5-lane group via shuffles ----------
    // All 32 lanes participate (full mask); idle lanes carry zeros.
    const int gb = lane - r;                   // group base lane
    unsigned maskAll = partAll;
    unsigned maskIB  = partIB;
#pragma unroll
    for (int j = 1; j < 5; ++j) {
        const int src = gb + ((r + j >= 5) ? (r + j - 5) : (r + j));
        maskAll |= __shfl_sync(0xFFFFFFFFu, partAll, src);
        maskIB  |= __shfl_sync(0xFFFFFFFFu, partIB,  src);
    }

    if (!active) return;

    maskAll |= (1u << 12);   // center: d forced 0, always passes, in-bounds
    maskIB  |= (1u << 12);

    // rare overflow: all 5 lanes of this point recompute exactly (cold fn)
    if (__popc(maskAll) > 5) {
        maskIB = knn_exact_top5(proj_range, x0, y0, ur);
    }

    // ---------------- phase 2: gather channel chunk r --------------------
    const int base = y0 * IMG_W + x0;

    int kk[5];
    {
        unsigned mm = maskIB;
#pragma unroll
        for (int i = 0; i < 5; ++i) {
            kk[i] = __ffs(mm) - 1;             // -1 when exhausted
            mm &= mm - 1;
        }
    }

    // accumulate on arrival (no float4 array -> fewer live registers)
    float4 acc = make_float4(0.f, 0.f, 0.f, 0.f);
#pragma unroll
    for (int i = 0; i < 5; ++i) {
        const int k  = kk[i];
        const int ky = (k * 205) >> 10;        // k/5 for k in [0,24]
        const int idx = base + k + ky * 2043 - 4098;  // = base+(ky-2)*W+(kx-2)
        if (k >= 0) {
            const float4 v = __ldg(probs4 + (size_t)idx * 5 + r);
            acc.x += v.x; acc.y += v.y; acc.z += v.z; acc.w += v.w;
        }
    }

    out4[(size_t)p * 5 + r] = acc;             // coalesced 80B per point
}

extern "C" void kernel_launch(void* const* d_in, const int* in_sizes, int n_in,
                              void* d_out, int out_size)
{
    const float*  proj_range = (const float*)  d_in[0];
    const float*  unproj     = (const float*)  d_in[1];
    const float4* probs4     = (const float4*) d_in[2];
    const int*    px         = (const int*)    d_in[3];
    const int*    py         = (const int*)    d_in[4];
    float4*       out4       = (float4*)       d_out;

    const int P = in_sizes[1];           // unproj_range element count
    const int blocks = (P + PTS_PER_BLK - 1) / PTS_PER_BLK;
    knn_fused<<<blocks, THREADS_FUSED>>>(proj_range, unproj, probs4,
                                         px, py, out4, P);
}